// round 8
// baseline (speedup 1.0000x reference)
#include <cuda_runtime.h>
#include <cuda_bf16.h>
#include <cuda_fp16.h>
#include <math.h>
#include <stdint.h>

// DeformableSpatialAttention — fp16 mma.sync, B-in-SMEM, fp16 conv staging
//   K0: pad + fp16 conv weights -> g_wBh[160][120]; biases -> g_bias
//   K1: channel mean+max reduce (float4, streaming) -> g_att(8,2,128,128)
//   K2: per image-row: im2col A(half) + B copy -> warp mma.sync fp16 GEMM
//       (128x160x112, 2 N-passes, B frags via LDS) -> bias/mask-sigmoid
//       (staged fp16) -> deformable sampling -> attmap.  111KB => 2 blk/SM.
//   K3: out = x * attmap; block = 1024px x 64ch, attmap in register.

#define Bn   8
#define Cn   256
#define Hn   128
#define Wn   128
#define HW   (Hn*Wn)
#define KK   49
#define NOFF 98
#define NCH  147
#define NP   160          // padded N (channels)
#define KS2  120          // k-stride in halves (240B rows)
#define CSH  132          // conv staging px-stride (halves)

__device__ float g_att[Bn*2*HW];
__device__ float g_attmap[Bn*HW];
__device__ __align__(16) __half g_wBh[NP*KS2];   // padded fp16 weights [n][k]
__device__ float g_bias[NP];

// ================= K0: weight prep =================
__global__ void dsa_prep_kernel(const float* __restrict__ ow, const float* __restrict__ ob,
                                const float* __restrict__ mw, const float* __restrict__ mb){
    int stride = gridDim.x * blockDim.x;
    for (int i = blockIdx.x*blockDim.x + threadIdx.x; i < NP*KS2; i += stride){
        int n = i / KS2;
        int k = i - n*KS2;
        float v = 0.f;
        if (k < NOFF){
            if      (n < NOFF) v = ow[n*NOFF + k];
            else if (n < NCH)  v = mw[(n-NOFF)*NOFF + k];
        }
        g_wBh[i] = __float2half_rn(v);
        if (k == 0)
            g_bias[n] = (n < NOFF) ? ob[n] : (n < NCH) ? mb[n-NOFF] : 0.f;
    }
}

// ================= K1: channel reduce (float4, streaming) =================
__global__ void dsa_reduce_kernel(const float* __restrict__ x){
    int t  = blockIdx.x * 256 + threadIdx.x;
    int b  = t >> 12;
    int p4 = t & 4095;
    const float4* base = (const float4*)x + (size_t)b*(Cn*HW/4) + p4;
    float4 s = make_float4(0.f,0.f,0.f,0.f);
    float4 m = make_float4(-1e30f,-1e30f,-1e30f,-1e30f);
    #pragma unroll 8
    for (int c = 0; c < Cn; c++){
        float4 v = __ldcs(base + c*(HW/4));
        s.x += v.x; s.y += v.y; s.z += v.z; s.w += v.w;
        m.x = fmaxf(m.x, v.x); m.y = fmaxf(m.y, v.y);
        m.z = fmaxf(m.z, v.z); m.w = fmaxf(m.w, v.w);
    }
    const float r = 1.f/256.f;
    float4 sm4 = make_float4(s.x*r, s.y*r, s.z*r, s.w*r);
    ((float4*)g_att)[b*(2*HW/4) + p4]        = sm4;
    ((float4*)g_att)[b*(2*HW/4) + HW/4 + p4] = m;
}

// ================= K2: fp16 mma.sync conv + deform =================
// SMEM layout (bytes)
#define SM_A     0                 // 128*120*2 = 30720 (half)
#define SM_B     30720             // 160*120*2 = 38400 -> 69120
#define SM_CONVH 69120             // 147*132*2 = 38808 -> pad 38816 -> 107936
#define SM_BIAS  107936            // 160*4 = 640 -> 108576
#define SM_DW    108576            // 98*4 -> pad 512 -> 109088
#define SM_PART  109088            // 512*4 = 2048 -> 111136
#define SM_TOTAL 111136

__device__ __forceinline__ void bilin2(const float* __restrict__ i0,
                                       const float* __restrict__ i1,
                                       float py, float px,
                                       float& s0, float& s1){
    float fy = floorf(py), fx = floorf(px);
    int y0 = (int)fy, x0 = (int)fx;
    int y1 = y0 + 1,  x1 = x0 + 1;
    float wy1 = py - fy, wy0 = 1.f - wy1;
    float wx1 = px - fx, wx0 = 1.f - wx1;
    float w00 = wy0*wx0, w01 = wy0*wx1, w10 = wy1*wx0, w11 = wy1*wx1;
    s0 = 0.f; s1 = 0.f;
    bool yv0 = (unsigned)y0 < (unsigned)Hn, yv1 = (unsigned)y1 < (unsigned)Hn;
    bool xv0 = (unsigned)x0 < (unsigned)Wn, xv1 = (unsigned)x1 < (unsigned)Wn;
    if (yv0 && xv0){ int o = (y0<<7)+x0; s0 += w00*i0[o]; s1 += w00*i1[o]; }
    if (yv0 && xv1){ int o = (y0<<7)+x1; s0 += w01*i0[o]; s1 += w01*i1[o]; }
    if (yv1 && xv0){ int o = (y1<<7)+x0; s0 += w10*i0[o]; s1 += w10*i1[o]; }
    if (yv1 && xv1){ int o = (y1<<7)+x1; s0 += w11*i0[o]; s1 += w11*i1[o]; }
}

__global__ __launch_bounds__(512, 2)
void dsa_conv_deform_kernel(const float* __restrict__ dconv_w){
    extern __shared__ char sm[];
    __half* Ash   = (__half*)(sm + SM_A);
    __half* Bsh   = (__half*)(sm + SM_B);
    __half* convh = (__half*)(sm + SM_CONVH);
    float* biass  = (float*)(sm + SM_BIAS);
    float* dws    = (float*)(sm + SM_DW);
    float* parts  = (float*)(sm + SM_PART);

    const int tid  = threadIdx.x;
    const int wid  = tid >> 5;
    const int lane = tid & 31;
    const int g    = lane >> 2;      // groupID (0..7)
    const int tig  = lane & 3;       // thread-in-group (0..3)
    const int b    = blockIdx.x >> 7;
    const int y    = blockIdx.x & 127;

    const float* att0 = g_att + ((b*2 + 0) << 14);
    const float* att1 = g_att + ((b*2 + 1) << 14);

    // ---- build im2col A (half) [128 px][120 k] straight from g_att ----
    {
        const int px = tid & 127;
        #pragma unroll
        for (int it = 0; it < 30; it++){
            int k = (tid >> 7) + it*4;          // 0..119
            float v = 0.f;
            if (k < NOFF){
                int c  = (k >= KK) ? 1 : 0;
                int r  = k - c*KK;
                int dy = r / 7;
                int dx = r - dy*7;
                int gy = y + dy - 3;
                int gx = px + dx - 3;
                if ((unsigned)gy < (unsigned)Hn && (unsigned)gx < (unsigned)Wn){
                    const float* src = c ? att1 : att0;
                    v = __ldg(src + (gy << 7) + gx);
                }
            }
            Ash[px*KS2 + k] = __float2half_rn(v);
        }
    }
    // ---- copy B weights into SMEM (coalesced float4) ----
    {
        const float4* src = (const float4*)g_wBh;
        float4* dst = (float4*)Bsh;
        #pragma unroll 5
        for (int i = tid; i < (NP*KS2*2)/16; i += 512) dst[i] = src[i];
    }
    if (tid < NP)   biass[tid] = g_bias[tid];
    if (tid < 2*KK) dws[tid]   = dconv_w[tid];
    __syncthreads();

    // ---- warp GEMM: 16 warps = 8(M)x2(N); per pass 16(M)x40(N), K=112 ----
    const int mrow  = (wid & 7) * 16;
    const int nbase = (wid >> 3) * 80;

    #pragma unroll 1
    for (int pass = 0; pass < 2; pass++){
        const int ncolp = nbase + pass*40;
        float acc[5][4];
        #pragma unroll
        for (int ni = 0; ni < 5; ni++)
            #pragma unroll
            for (int j = 0; j < 4; j++) acc[ni][j] = 0.f;

        #pragma unroll
        for (int ks = 0; ks < 7; ks++){
            const int k0 = ks*16;
            const uint32_t a0 = *(const uint32_t*)(Ash + (mrow+g  )*KS2 + k0 + 2*tig    );
            const uint32_t a1 = *(const uint32_t*)(Ash + (mrow+8+g)*KS2 + k0 + 2*tig    );
            const uint32_t a2 = *(const uint32_t*)(Ash + (mrow+g  )*KS2 + k0 + 2*tig + 8);
            const uint32_t a3 = *(const uint32_t*)(Ash + (mrow+8+g)*KS2 + k0 + 2*tig + 8);
            #pragma unroll
            for (int ni = 0; ni < 5; ni++){
                const int n0 = ncolp + ni*8;
                const __half* bp = Bsh + (n0+g)*KS2 + k0 + 2*tig;
                uint32_t b0 = *(const uint32_t*)bp;
                uint32_t b1 = *(const uint32_t*)(bp + 8);
                asm volatile(
                    "mma.sync.aligned.m16n8k16.row.col.f32.f16.f16.f32 "
                    "{%0,%1,%2,%3}, {%4,%5,%6,%7}, {%8,%9}, {%0,%1,%2,%3};"
                    : "+f"(acc[ni][0]), "+f"(acc[ni][1]),
                      "+f"(acc[ni][2]), "+f"(acc[ni][3])
                    : "r"(a0), "r"(a1), "r"(a2), "r"(a3), "r"(b0), "r"(b1));
            }
        }

        // ---- per-pass epilogue: bias + mask sigmoid -> convh[ch][px] ----
        #pragma unroll
        for (int ni = 0; ni < 5; ni++){
            const int n0 = ncolp + ni*8 + 2*tig;
            #pragma unroll
            for (int j = 0; j < 4; j++){
                int ch = n0 + (j & 1);
                int px = mrow + g + ((j >> 1) << 3);
                if (ch < NCH){
                    float v = acc[ni][j] + biass[ch];
                    if (ch >= NOFF) v = 2.f/(1.f + __expf(-v));
                    convh[ch*CSH + px] = __float2half_rn(v);
                }
            }
        }
    }
    __syncthreads();

    // ---- deformable sampling: 4 ways x 128 px ----
    {
        const int way = tid >> 7;
        const int px  = tid & 127;
        float part = 0.f;
        #pragma unroll 2
        for (int kk = way; kk < KK; kk += 4){
            float oy = __half2float(convh[(2*kk  )*CSH + px]);
            float ox = __half2float(convh[(2*kk+1)*CSH + px]);
            float mk = __half2float(convh[(NOFF+kk)*CSH + px]);
            float py = (float)(y + kk/7 - 3) + oy;
            float pxx= (float)(px + kk%7 - 3) + ox;
            float s0, s1;
            bilin2(att0, att1, py, pxx, s0, s1);
            part += (s0*dws[kk] + s1*dws[KK+kk]) * mk;
        }
        parts[way*128 + px] = part;
    }
    __syncthreads();

    if (tid < 128){
        float d = parts[tid] + parts[128+tid] + parts[256+tid] + parts[384+tid];
        g_attmap[(b << 14) + (y << 7) + tid] = 1.f/(1.f + __expf(-d));
    }
}

// ================= K3: out = x * attmap =================
// grid 512: blk -> b (8) x tile (16 x 1024px) x cgrp (4 x 64ch)
__global__ __launch_bounds__(256)
void dsa_mul_kernel(const float* __restrict__ x,
                    float* __restrict__ out){
    const int blk  = blockIdx.x;
    const int b    = blk >> 6;
    const int tile = (blk >> 2) & 15;
    const int c0   = (blk & 3) * 64;
    const int p4   = tile*256 + threadIdx.x;        // float4 idx in plane (0..4095)

    float4 a = *(const float4*)(g_attmap + (b << 14) + (p4 << 2));

    const float4* xp = (const float4*)x + ((size_t)b*Cn + c0)*(HW/4) + p4;
    float4*       op = (float4*)out     + ((size_t)b*Cn + c0)*(HW/4) + p4;
    #pragma unroll 4
    for (int c = 0; c < 64; c++){
        float4 v = __ldcs(xp + c*(HW/4));
        v.x *= a.x; v.y *= a.y; v.z *= a.z; v.w *= a.w;
        __stcs(op + c*(HW/4), v);
    }
}

// ================= launch =================
extern "C" void kernel_launch(void* const* d_in, const int* in_sizes, int n_in,
                              void* d_out, int out_size){
    const float* x        = (const float*)d_in[0];
    const float* offset_w = (const float*)d_in[1];
    const float* offset_b = (const float*)d_in[2];
    const float* mod_w    = (const float*)d_in[3];
    const float* mod_b    = (const float*)d_in[4];
    const float* dconv_w  = (const float*)d_in[5];
    float* out = (float*)d_out;

    cudaFuncSetAttribute(dsa_conv_deform_kernel,
                         cudaFuncAttributeMaxDynamicSharedMemorySize, SM_TOTAL);

    dsa_prep_kernel<<<16, 512>>>(offset_w, offset_b, mod_w, mod_b);
    dsa_reduce_kernel<<<128, 256>>>(x);
    dsa_conv_deform_kernel<<<Bn*Hn, 512, SM_TOTAL>>>(dconv_w);
    dsa_mul_kernel<<<512, 256>>>(x, out);
}